// round 4
// baseline (speedup 1.0000x reference)
#include <cuda_runtime.h>
#include <math.h>

#define B_ 2
#define S_ 4096
#define E_ 1024
#define D_ 64
#define WIN_ 5
#define DIL_ 2

// Scratch (allocation-free rule: __device__ globals)
__device__ float g_Q[B_ * S_ * D_];
__device__ float g_K[B_ * S_ * D_];
__device__ float g_V[B_ * S_ * D_];
__device__ float g_part[B_ * 16 * D_];     // partial V row-sums
__device__ float g_Whi[3 * E_ * D_];       // pre-split weights (tf32 hi)
__device__ float g_Wlo[3 * E_ * D_];       // residual (lo)

// ---------------------------------------------------------------------------
// tf32 helpers
// ---------------------------------------------------------------------------
__device__ __forceinline__ unsigned f2tf32(float f) {
    unsigned r;
    asm("cvt.rna.tf32.f32 %0, %1;" : "=r"(r) : "f"(f));
    return r;
}

__device__ __forceinline__ void mma_tf32(float* c, const unsigned* a, const unsigned* b) {
    asm volatile(
        "mma.sync.aligned.m16n8k8.row.col.f32.tf32.tf32.f32 "
        "{%0,%1,%2,%3}, {%4,%5,%6,%7}, {%8,%9}, {%0,%1,%2,%3};"
        : "+f"(c[0]), "+f"(c[1]), "+f"(c[2]), "+f"(c[3])
        : "r"(a[0]), "r"(a[1]), "r"(a[2]), "r"(a[3]), "r"(b[0]), "r"(b[1]));
}

// ---------------------------------------------------------------------------
// Kernel 0: one-shot weight split (Wq|Wk|Wv -> hi/lo planes).
// 3*1024*64 = 196608 elements. grid 192 x 1024 threads? use 768 x 256.
// ---------------------------------------------------------------------------
__global__ void wsplit_kernel(const float* __restrict__ Wq,
                              const float* __restrict__ Wk,
                              const float* __restrict__ Wv)
{
    const int idx = blockIdx.x * blockDim.x + threadIdx.x;
    if (idx >= 3 * E_ * D_) return;
    const int which = idx / (E_ * D_);
    const int off = idx - which * (E_ * D_);
    const float* src = (which == 0) ? Wq : (which == 1) ? Wk : Wv;
    const float v = src[off];
    const unsigned h = f2tf32(v);
    g_Whi[idx] = __uint_as_float(h);
    g_Wlo[idx] = v - __uint_as_float(h);
}

// ---------------------------------------------------------------------------
// Kernel 1: QKV projection GEMM, 3xTF32 tensor-core path.
// C[8192 x 64] = x[8192 x 1024] @ W[1024 x 64] + bias, W selected by blockIdx.y.
// BM=64, BN=64, BK=16, 256 threads = 8 warps (4m x 2n), warp tile 16x32.
// A split to hi/lo at smem-store time; B pre-split in global (g_Whi/g_Wlo).
// Ping-pong smem stages: ONE __syncthreads per K-tile.
// ---------------------------------------------------------------------------
#define BM 64
#define BN 64
#define BK 16
#define PADA 20
#define PADB 72

__global__ __launch_bounds__(256) void qkv_gemm_tf32(
    const float* __restrict__ x,
    const float* __restrict__ bq,
    const float* __restrict__ bk,
    const float* __restrict__ bv)
{
    const float* bias;
    float* out;
    if (blockIdx.y == 0)      { bias = bq; out = g_Q; }
    else if (blockIdx.y == 1) { bias = bk; out = g_K; }
    else                      { bias = bv; out = g_V; }
    const float* Whi = g_Whi + (size_t)blockIdx.y * E_ * D_;
    const float* Wlo = g_Wlo + (size_t)blockIdx.y * E_ * D_;

    __shared__ float As_hi[2][BM][PADA];
    __shared__ float As_lo[2][BM][PADA];
    __shared__ float Bs_hi[2][BK][PADB];
    __shared__ float Bs_lo[2][BK][PADB];

    const int tid  = threadIdx.x;
    const int lane = tid & 31;
    const int wid  = tid >> 5;
    const int wm   = wid >> 1;     // 0..3
    const int wn   = wid & 1;      // 0..1
    const int rowBase = blockIdx.x * BM;

    // global load coordinates
    const int arow = tid >> 2;          // 0..63
    const int ak4  = (tid & 3) * 4;     // 0,4,8,12
    const int bkr  = tid >> 4;          // 0..15
    const int bn4  = (tid & 15) * 4;    // 0..60

    const float* aptr  = x   + (size_t)(rowBase + arow) * E_ + ak4;
    const float* bptrh = Whi + (size_t)bkr * D_ + bn4;
    const float* bptrl = Wlo + (size_t)bkr * D_ + bn4;

    float acc[4][4];
#pragma unroll
    for (int nt = 0; nt < 4; nt++)
#pragma unroll
        for (int k = 0; k < 4; k++) acc[nt][k] = 0.f;

    const int r  = lane >> 2;
    const int cc = lane & 3;
    const int m0 = wm * 16;

    float4 pa, pbh, pbl;

    auto store_tile = [&](int st) {
        float4 h, l;
        h.x = __uint_as_float(f2tf32(pa.x)); l.x = pa.x - h.x;
        h.y = __uint_as_float(f2tf32(pa.y)); l.y = pa.y - h.y;
        h.z = __uint_as_float(f2tf32(pa.z)); l.z = pa.z - h.z;
        h.w = __uint_as_float(f2tf32(pa.w)); l.w = pa.w - h.w;
        *(float4*)&As_hi[st][arow][ak4] = h;
        *(float4*)&As_lo[st][arow][ak4] = l;
        *(float4*)&Bs_hi[st][bkr][bn4] = pbh;
        *(float4*)&Bs_lo[st][bkr][bn4] = pbl;
    };

    auto compute_tile = [&](int st) {
#pragma unroll
        for (int ks = 0; ks < 2; ks++) {
            const int kb = ks * 8;
            unsigned ah[4], al[4];
            ah[0] = __float_as_uint(As_hi[st][m0 + r][kb + cc]);
            ah[1] = __float_as_uint(As_hi[st][m0 + r + 8][kb + cc]);
            ah[2] = __float_as_uint(As_hi[st][m0 + r][kb + cc + 4]);
            ah[3] = __float_as_uint(As_hi[st][m0 + r + 8][kb + cc + 4]);
            al[0] = __float_as_uint(As_lo[st][m0 + r][kb + cc]);
            al[1] = __float_as_uint(As_lo[st][m0 + r + 8][kb + cc]);
            al[2] = __float_as_uint(As_lo[st][m0 + r][kb + cc + 4]);
            al[3] = __float_as_uint(As_lo[st][m0 + r + 8][kb + cc + 4]);
            // convert lo residual to tf32 once here (cheap: 4 cvt)
#pragma unroll
            for (int i = 0; i < 4; i++) al[i] = f2tf32(__uint_as_float(al[i]));

            unsigned bh[4][2], bl[4][2];
#pragma unroll
            for (int nt = 0; nt < 4; nt++) {
                const int n0 = wn * 32 + nt * 8;
                bh[nt][0] = __float_as_uint(Bs_hi[st][kb + cc][n0 + r]);
                bh[nt][1] = __float_as_uint(Bs_hi[st][kb + cc + 4][n0 + r]);
                bl[nt][0] = f2tf32(Bs_lo[st][kb + cc][n0 + r]);
                bl[nt][1] = f2tf32(Bs_lo[st][kb + cc + 4][n0 + r]);
            }
#pragma unroll
            for (int nt = 0; nt < 4; nt++) {
                mma_tf32(acc[nt], ah, bh[nt]);   // hi*hi
                mma_tf32(acc[nt], al, bh[nt]);   // lo*hi
                mma_tf32(acc[nt], ah, bl[nt]);   // hi*lo
            }
        }
    };

    // prologue: tile 0 -> stage 0
    pa  = *(const float4*)(aptr);
    pbh = *(const float4*)(bptrh);
    pbl = *(const float4*)(bptrl);
    store_tile(0);
    __syncthreads();

    const int KTILES = E_ / BK;   // 64
    for (int kt = 1; kt < KTILES; kt++) {
        // prefetch tile kt into registers
        pa  = *(const float4*)(aptr + kt * BK);
        pbh = *(const float4*)(bptrh + (size_t)kt * BK * D_);
        pbl = *(const float4*)(bptrl + (size_t)kt * BK * D_);

        compute_tile((kt - 1) & 1);
        store_tile(kt & 1);           // other buffer: safe, fenced by prev sync
        __syncthreads();
    }
    compute_tile((KTILES - 1) & 1);

    // epilogue: bias + store
#pragma unroll
    for (int nt = 0; nt < 4; nt++) {
        const int col = wn * 32 + nt * 8 + 2 * cc;
        const float b0v = bias[col];
        const float b1v = bias[col + 1];
        const int row0 = rowBase + m0 + r;
        float2 v0 = make_float2(acc[nt][0] + b0v, acc[nt][1] + b1v);
        float2 v1 = make_float2(acc[nt][2] + b0v, acc[nt][3] + b1v);
        *(float2*)&out[(size_t)row0 * D_ + col] = v0;
        *(float2*)&out[(size_t)(row0 + 8) * D_ + col] = v1;
    }
}

// ---------------------------------------------------------------------------
// Kernel 2: per-batch partial V row-sums. grid = B*16, block = (64, 4).
// ---------------------------------------------------------------------------
__global__ void vsum_partial()
{
    __shared__ float sm[4][D_];
    const int b = blockIdx.x >> 4;
    const int p = blockIdx.x & 15;
    const int d = threadIdx.x;
    const int g = threadIdx.y;

    float s = 0.f;
    const float* base = g_V + ((size_t)b * S_ + (size_t)p * 256 + g) * D_ + d;
#pragma unroll 8
    for (int rr = 0; rr < 64; rr++) s += base[(size_t)rr * 4 * D_];
    sm[g][d] = s;
    __syncthreads();
    if (g == 0) {
        float t = sm[0][d] + sm[1][d] + sm[2][d] + sm[3][d];
        g_part[(b * 16 + p) * D_ + d] = t;
    }
}

// ---------------------------------------------------------------------------
// Kernel 3: windowed attention combine. One warp per (b, i).
// ---------------------------------------------------------------------------
__global__ __launch_bounds__(256) void attn_kernel(float* __restrict__ out)
{
    const int gw = (blockIdx.x * blockDim.x + threadIdx.x) >> 5;
    const int lane = threadIdx.x & 31;
    if (gw >= B_ * S_) return;

    const int b = gw >> 12;
    const int i = gw & (S_ - 1);

    const float* Qr = g_Q + (size_t)gw * D_;
    const float q0 = Qr[lane];
    const float q1 = Qr[lane + 32];

    float c[WIN_];
    bool valid[WIN_];
    int jv[WIN_];
    int nv = 0;
    float cmax = 0.f;

#pragma unroll
    for (int w = 0; w < WIN_; w++) {
        const int j = i + DIL_ * (w - WIN_ / 2);
        jv[w] = j;
        valid[w] = (j >= 0) && (j < S_);
        float p = 0.f;
        if (valid[w]) {
            const float* Kr = g_K + ((size_t)b * S_ + j) * D_;
            p = q0 * Kr[lane] + q1 * Kr[lane + 32];
#pragma unroll
            for (int o = 16; o > 0; o >>= 1)
                p += __shfl_xor_sync(0xffffffffu, p, o);
            nv++;
            cmax = fmaxf(cmax, p);
        }
        c[w] = p;
    }

    float vs0 = 0.f, vs1 = 0.f;
    const float* pp = g_part + b * 16 * D_;
#pragma unroll
    for (int p = 0; p < 16; p++) {
        vs0 += pp[p * D_ + lane];
        vs1 += pp[p * D_ + lane + 32];
    }

    const float e0 = expf(-cmax);
    float denom = e0 * (float)(S_ - nv);
    float acc0 = e0 * vs0;
    float acc1 = e0 * vs1;

#pragma unroll
    for (int w = 0; w < WIN_; w++) {
        if (valid[w]) {
            const float ew = expf(c[w] - cmax);
            denom += ew;
            const float f = ew - e0;
            const float* Vr = g_V + ((size_t)b * S_ + jv[w]) * D_;
            acc0 = fmaf(f, Vr[lane], acc0);
            acc1 = fmaf(f, Vr[lane + 32], acc1);
        }
    }

    const float inv = 1.f / denom;
    out[(size_t)gw * D_ + lane] = acc0 * inv;
    out[(size_t)gw * D_ + lane + 32] = acc1 * inv;
}

// ---------------------------------------------------------------------------
extern "C" void kernel_launch(void* const* d_in, const int* in_sizes, int n_in,
                              void* d_out, int out_size)
{
    const float* x  = (const float*)d_in[0];
    const float* Wq = (const float*)d_in[1];
    const float* bq = (const float*)d_in[2];
    const float* Wk = (const float*)d_in[3];
    const float* bk = (const float*)d_in[4];
    const float* Wv = (const float*)d_in[5];
    const float* bv = (const float*)d_in[6];
    float* out = (float*)d_out;

    wsplit_kernel<<<(3 * E_ * D_ + 255) / 256, 256>>>(Wq, Wk, Wv);

    dim3 gg((B_ * S_) / BM, 3);
    qkv_gemm_tf32<<<gg, 256>>>(x, bq, bk, bv);

    vsum_partial<<<B_ * 16, dim3(D_, 4)>>>();

    const int warps = B_ * S_;
    attn_kernel<<<(warps * 32 + 255) / 256, 256>>>(out);
}

// round 6
// speedup vs baseline: 1.0003x; 1.0003x over previous
#include <cuda_runtime.h>
#include <math.h>

#define B_ 2
#define S_ 4096
#define E_ 1024
#define D_ 64
#define WIN_ 5
#define DIL_ 2

// Scratch (allocation-free rule: __device__ globals)
__device__ float g_Q[B_ * S_ * D_];
__device__ float g_K[B_ * S_ * D_];
__device__ float g_V[B_ * S_ * D_];
__device__ float g_part[B_ * 16 * D_];
__device__ float g_Whi[3 * E_ * D_];   // W tf32-rounded hi   [mat][k][n]
__device__ float g_Wlo[3 * E_ * D_];   // tf32-rounded residual

// ---------------------------------------------------------------------------
// tf32 helpers
// ---------------------------------------------------------------------------
__device__ __forceinline__ unsigned f2tf32(float f) {
    unsigned r;
    asm("cvt.rna.tf32.f32 %0, %1;" : "=r"(r) : "f"(f));
    return r;
}

__device__ __forceinline__ void mma_tf32(float* c, const unsigned* a, const unsigned* b) {
    asm volatile(
        "mma.sync.aligned.m16n8k8.row.col.f32.tf32.tf32.f32 "
        "{%0,%1,%2,%3}, {%4,%5,%6,%7}, {%8,%9}, {%0,%1,%2,%3};"
        : "+f"(c[0]), "+f"(c[1]), "+f"(c[2]), "+f"(c[3])
        : "r"(a[0]), "r"(a[1]), "r"(a[2]), "r"(a[3]), "r"(b[0]), "r"(b[1]));
}

// ---------------------------------------------------------------------------
// Kernel 0: one-shot weight split (Wq|Wk|Wv -> tf32 hi/lo planes, both cvt'd).
// ---------------------------------------------------------------------------
__global__ void wsplit_kernel(const float* __restrict__ Wq,
                              const float* __restrict__ Wk,
                              const float* __restrict__ Wv)
{
    const int idx = blockIdx.x * blockDim.x + threadIdx.x;
    if (idx >= 3 * E_ * D_) return;
    const int which = idx >> 16;              // / (E_*D_)
    const int off = idx & 0xFFFF;
    const float* src = (which == 0) ? Wq : (which == 1) ? Wk : Wv;
    const float v = src[off];
    const float h = __uint_as_float(f2tf32(v));
    g_Whi[idx] = h;
    g_Wlo[idx] = __uint_as_float(f2tf32(v - h));   // residual, pre-rounded to tf32
}

// ---------------------------------------------------------------------------
// Kernel 1: QKV projection GEMM, 3xTF32 tensor-core path.
// C[8192 x 64] = x[8192 x 1024] @ W[1024 x 64] + bias, W selected by blockIdx.y.
// BM=64, BN=64, BK=16, 256 threads = 8 warps (4m x 2n), warp tile 16x32.
// Inner loop is PURE LDS+MMA: A hi/lo split+cvt at STS time, W planes
// pre-converted in global memory. Ping-pong smem, one __syncthreads per tile.
// MMA issue order hh[0..3], lh[0..3], hl[0..3] -> dep distance 4.
// ---------------------------------------------------------------------------
#define BM 64
#define BN 64
#define BK 16
#define PADA 20
#define PADB 72

__global__ __launch_bounds__(256) void qkv_gemm_tf32(
    const float* __restrict__ x,
    const float* __restrict__ bq,
    const float* __restrict__ bk,
    const float* __restrict__ bv)
{
    const float* bias;
    float* out;
    if (blockIdx.y == 0)      { bias = bq; out = g_Q; }
    else if (blockIdx.y == 1) { bias = bk; out = g_K; }
    else                      { bias = bv; out = g_V; }
    const float* Whi = g_Whi + (size_t)blockIdx.y * E_ * D_;
    const float* Wlo = g_Wlo + (size_t)blockIdx.y * E_ * D_;

    __shared__ unsigned As_hi[2][BM][PADA];
    __shared__ unsigned As_lo[2][BM][PADA];
    __shared__ unsigned Bs_hi[2][BK][PADB];
    __shared__ unsigned Bs_lo[2][BK][PADB];

    const int tid  = threadIdx.x;
    const int lane = tid & 31;
    const int wid  = tid >> 5;
    const int wm   = wid >> 1;     // 0..3
    const int wn   = wid & 1;      // 0..1
    const int rowBase = blockIdx.x * BM;

    // global load coordinates
    const int arow = tid >> 2;          // 0..63
    const int ak4  = (tid & 3) * 4;     // 0,4,8,12
    const int bkr  = tid >> 4;          // 0..15
    const int bn4  = (tid & 15) * 4;    // 0..60

    const float* aptr  = x   + (size_t)(rowBase + arow) * E_ + ak4;
    const float* bptrh = Whi + (size_t)bkr * D_ + bn4;
    const float* bptrl = Wlo + (size_t)bkr * D_ + bn4;

    float acc[4][4];
#pragma unroll
    for (int nt = 0; nt < 4; nt++)
#pragma unroll
        for (int k = 0; k < 4; k++) acc[nt][k] = 0.f;

    const int r  = lane >> 2;
    const int cc = lane & 3;
    const int m0 = wm * 16;

    float4 pa, pbh, pbl;

    auto store_tile = [&](int st) {
        uint4 h, l;
        h.x = f2tf32(pa.x); l.x = f2tf32(pa.x - __uint_as_float(h.x));
        h.y = f2tf32(pa.y); l.y = f2tf32(pa.y - __uint_as_float(h.y));
        h.z = f2tf32(pa.z); l.z = f2tf32(pa.z - __uint_as_float(h.z));
        h.w = f2tf32(pa.w); l.w = f2tf32(pa.w - __uint_as_float(h.w));
        *(uint4*)&As_hi[st][arow][ak4] = h;
        *(uint4*)&As_lo[st][arow][ak4] = l;
        *(float4*)&Bs_hi[st][bkr][bn4] = pbh;
        *(float4*)&Bs_lo[st][bkr][bn4] = pbl;
    };

    auto compute_tile = [&](int st) {
#pragma unroll
        for (int ks = 0; ks < 2; ks++) {
            const int kb = ks * 8;
            unsigned ah[4], al[4];
            ah[0] = As_hi[st][m0 + r][kb + cc];
            ah[1] = As_hi[st][m0 + r + 8][kb + cc];
            ah[2] = As_hi[st][m0 + r][kb + cc + 4];
            ah[3] = As_hi[st][m0 + r + 8][kb + cc + 4];
            al[0] = As_lo[st][m0 + r][kb + cc];
            al[1] = As_lo[st][m0 + r + 8][kb + cc];
            al[2] = As_lo[st][m0 + r][kb + cc + 4];
            al[3] = As_lo[st][m0 + r + 8][kb + cc + 4];

            unsigned bh[4][2], bl[4][2];
#pragma unroll
            for (int nt = 0; nt < 4; nt++) {
                const int n0 = wn * 32 + nt * 8;
                bh[nt][0] = Bs_hi[st][kb + cc][n0 + r];
                bh[nt][1] = Bs_hi[st][kb + cc + 4][n0 + r];
                bl[nt][0] = Bs_lo[st][kb + cc][n0 + r];
                bl[nt][1] = Bs_lo[st][kb + cc + 4][n0 + r];
            }
            // dep distance 4: all hh, then all lh, then all hl
#pragma unroll
            for (int nt = 0; nt < 4; nt++) mma_tf32(acc[nt], ah, bh[nt]);
#pragma unroll
            for (int nt = 0; nt < 4; nt++) mma_tf32(acc[nt], al, bh[nt]);
#pragma unroll
            for (int nt = 0; nt < 4; nt++) mma_tf32(acc[nt], ah, bl[nt]);
        }
    };

    // prologue: tile 0 -> stage 0
    pa  = *(const float4*)(aptr);
    pbh = *(const float4*)(bptrh);
    pbl = *(const float4*)(bptrl);
    store_tile(0);
    __syncthreads();

    const int KTILES = E_ / BK;   // 64
    for (int kt = 1; kt < KTILES; kt++) {
        pa  = *(const float4*)(aptr + kt * BK);
        pbh = *(const float4*)(bptrh + (size_t)kt * BK * D_);
        pbl = *(const float4*)(bptrl + (size_t)kt * BK * D_);

        compute_tile((kt - 1) & 1);
        store_tile(kt & 1);           // other buffer: fenced by previous sync
        __syncthreads();
    }
    compute_tile((KTILES - 1) & 1);

    // epilogue: bias + store
#pragma unroll
    for (int nt = 0; nt < 4; nt++) {
        const int col = wn * 32 + nt * 8 + 2 * cc;
        const float b0v = bias[col];
        const float b1v = bias[col + 1];
        const int row0 = rowBase + m0 + r;
        float2 v0 = make_float2(acc[nt][0] + b0v, acc[nt][1] + b1v);
        float2 v1 = make_float2(acc[nt][2] + b0v, acc[nt][3] + b1v);
        *(float2*)&out[(size_t)row0 * D_ + col] = v0;
        *(float2*)&out[(size_t)(row0 + 8) * D_ + col] = v1;
    }
}

// ---------------------------------------------------------------------------
// Kernel 2: per-batch partial V row-sums. grid = B*16, block = (64, 4).
// ---------------------------------------------------------------------------
__global__ void vsum_partial()
{
    __shared__ float sm[4][D_];
    const int b = blockIdx.x >> 4;
    const int p = blockIdx.x & 15;
    const int d = threadIdx.x;
    const int g = threadIdx.y;

    float s = 0.f;
    const float* base = g_V + ((size_t)b * S_ + (size_t)p * 256 + g) * D_ + d;
#pragma unroll 8
    for (int rr = 0; rr < 64; rr++) s += base[(size_t)rr * 4 * D_];
    sm[g][d] = s;
    __syncthreads();
    if (g == 0) {
        float t = sm[0][d] + sm[1][d] + sm[2][d] + sm[3][d];
        g_part[(b * 16 + p) * D_ + d] = t;
    }
}

// ---------------------------------------------------------------------------
// Kernel 3: windowed attention combine. One warp per (b, i).
// out[i] = [ e0*Vsum + sum_w (e_w - e0)*V[j_w] ] / [ sum_w e_w + e0*(S - n_valid) ]
// ---------------------------------------------------------------------------
__global__ __launch_bounds__(256) void attn_kernel(float* __restrict__ out)
{
    const int gw = (blockIdx.x * blockDim.x + threadIdx.x) >> 5;
    const int lane = threadIdx.x & 31;
    if (gw >= B_ * S_) return;

    const int b = gw >> 12;
    const int i = gw & (S_ - 1);

    const float* Qr = g_Q + (size_t)gw * D_;
    const float q0 = Qr[lane];
    const float q1 = Qr[lane + 32];

    float c[WIN_];
    bool valid[WIN_];
    int jv[WIN_];
    int nv = 0;
    float cmax = 0.f;

#pragma unroll
    for (int w = 0; w < WIN_; w++) {
        const int j = i + DIL_ * (w - WIN_ / 2);
        jv[w] = j;
        valid[w] = (j >= 0) && (j < S_);
        float p = 0.f;
        if (valid[w]) {
            const float* Kr = g_K + ((size_t)b * S_ + j) * D_;
            p = q0 * Kr[lane] + q1 * Kr[lane + 32];
#pragma unroll
            for (int o = 16; o > 0; o >>= 1)
                p += __shfl_xor_sync(0xffffffffu, p, o);
            nv++;
            cmax = fmaxf(cmax, p);
        }
        c[w] = p;
    }

    float vs0 = 0.f, vs1 = 0.f;
    const float* pp = g_part + b * 16 * D_;
#pragma unroll
    for (int p = 0; p < 16; p++) {
        vs0 += pp[p * D_ + lane];
        vs1 += pp[p * D_ + lane + 32];
    }

    const float e0 = expf(-cmax);
    float denom = e0 * (float)(S_ - nv);
    float acc0 = e0 * vs0;
    float acc1 = e0 * vs1;

#pragma unroll
    for (int w = 0; w < WIN_; w++) {
        if (valid[w]) {
            const float ew = expf(c[w] - cmax);
            denom += ew;
            const float f = ew - e0;
            const float* Vr = g_V + ((size_t)b * S_ + jv[w]) * D_;
            acc0 = fmaf(f, Vr[lane], acc0);
            acc1 = fmaf(f, Vr[lane + 32], acc1);
        }
    }

    const float inv = 1.f / denom;
    out[(size_t)gw * D_ + lane] = acc0 * inv;
    out[(size_t)gw * D_ + lane + 32] = acc1 * inv;
}

// ---------------------------------------------------------------------------
extern "C" void kernel_launch(void* const* d_in, const int* in_sizes, int n_in,
                              void* d_out, int out_size)
{
    const float* x  = (const float*)d_in[0];
    const float* Wq = (const float*)d_in[1];
    const float* bq = (const float*)d_in[2];
    const float* Wk = (const float*)d_in[3];
    const float* bk = (const float*)d_in[4];
    const float* Wv = (const float*)d_in[5];
    const float* bv = (const float*)d_in[6];
    float* out = (float*)d_out;

    wsplit_kernel<<<(3 * E_ * D_ + 255) / 256, 256>>>(Wq, Wk, Wv);

    dim3 gg((B_ * S_) / BM, 3);
    qkv_gemm_tf32<<<gg, 256>>>(x, bq, bk, bv);

    vsum_partial<<<B_ * 16, dim3(D_, 4)>>>();

    const int warps = B_ * S_;
    attn_kernel<<<(warps * 32 + 255) / 256, 256>>>(out);
}

// round 7
// speedup vs baseline: 1.2293x; 1.2289x over previous
#include <cuda_runtime.h>
#include <cuda_bf16.h>
#include <math.h>

#define B_ 2
#define S_ 4096
#define E_ 1024
#define D_ 64
#define WIN_ 5
#define DIL_ 2

// Scratch (allocation-free rule: __device__ globals)
__device__ float g_Q[B_ * S_ * D_];
__device__ float g_K[B_ * S_ * D_];
__device__ float g_V[B_ * S_ * D_];
__device__ float g_part[B_ * 16 * D_];
// x split into packed bf16 pairs (u32 = {k+1 | k}), [row][k/2]
__device__ unsigned g_xhi[B_ * S_ * (E_ / 2)];
__device__ unsigned g_xlo[B_ * S_ * (E_ / 2)];
// W split into packed bf16 pairs, [mat][k/2][n]
__device__ unsigned g_Wbhi[3 * (E_ / 2) * D_];
__device__ unsigned g_Wblo[3 * (E_ / 2) * D_];

// ---------------------------------------------------------------------------
// bf16 helpers
// ---------------------------------------------------------------------------
__device__ __forceinline__ unsigned pack_bf16(float lo_val, float hi_val) {
    __nv_bfloat162 p;
    p.x = __float2bfloat16(lo_val);   // low 16 bits  (k even)
    p.y = __float2bfloat16(hi_val);   // high 16 bits (k odd)
    return *(unsigned*)&p;
}
__device__ __forceinline__ float bf_residual(float v) {
    __nv_bfloat16 h = __float2bfloat16(v);
    return v - __bfloat162float(h);
}

__device__ __forceinline__ void mma_bf16(float* c, const unsigned* a, const unsigned* b) {
    asm volatile(
        "mma.sync.aligned.m16n8k16.row.col.f32.bf16.bf16.f32 "
        "{%0,%1,%2,%3}, {%4,%5,%6,%7}, {%8,%9}, {%0,%1,%2,%3};"
        : "+f"(c[0]), "+f"(c[1]), "+f"(c[2]), "+f"(c[3])
        : "r"(a[0]), "r"(a[1]), "r"(a[2]), "r"(a[3]), "r"(b[0]), "r"(b[1]));
}

// ---------------------------------------------------------------------------
// Kernel 0a: x -> packed bf16 hi/lo planes. grid = B*S, block = 256.
// ---------------------------------------------------------------------------
__global__ void xsplit_kernel(const float* __restrict__ x)
{
    const int row = blockIdx.x;
    const int t = threadIdx.x;
    float4 v = *(const float4*)(x + (size_t)row * E_ + t * 4);
    uint2 h, l;
    h.x = pack_bf16(v.x, v.y);
    h.y = pack_bf16(v.z, v.w);
    l.x = pack_bf16(bf_residual(v.x), bf_residual(v.y));
    l.y = pack_bf16(bf_residual(v.z), bf_residual(v.w));
    *(uint2*)&g_xhi[(size_t)row * (E_ / 2) + t * 2] = h;
    *(uint2*)&g_xlo[(size_t)row * (E_ / 2) + t * 2] = l;
}

// ---------------------------------------------------------------------------
// Kernel 0b: W -> packed bf16 hi/lo planes, [mat][k/2][n].
// ---------------------------------------------------------------------------
__global__ void wsplit_kernel(const float* __restrict__ Wq,
                              const float* __restrict__ Wk,
                              const float* __restrict__ Wv)
{
    const int idx = blockIdx.x * blockDim.x + threadIdx.x;
    if (idx >= 3 * (E_ / 2) * D_) return;
    const int mat = idx / ((E_ / 2) * D_);
    const int rem = idx - mat * ((E_ / 2) * D_);
    const int k2 = rem >> 6;
    const int n = rem & 63;
    const float* src = (mat == 0) ? Wq : (mat == 1) ? Wk : Wv;
    const float v0 = src[(2 * k2) * D_ + n];
    const float v1 = src[(2 * k2 + 1) * D_ + n];
    g_Wbhi[idx] = pack_bf16(v0, v1);
    g_Wblo[idx] = pack_bf16(bf_residual(v0), bf_residual(v1));
}

// ---------------------------------------------------------------------------
// Kernel 1: QKV projection GEMM, 3xBF16 (hh+lh+hl) on m16n8k16 tensor cores.
// C[8192 x 64] = x[8192 x 1024] @ W[1024 x 64] + bias, W selected by blockIdx.y.
// BM=64, BN=64, BK=16, 256 threads = 8 warps (4m x 2n), warp tile 16x32.
// All operands pre-converted; inner loop pure LDG/STS/LDS/MMA.
// ---------------------------------------------------------------------------
#define BM 64
#define BK 16

__global__ __launch_bounds__(256) void qkv_gemm_bf16(
    const float* __restrict__ bq,
    const float* __restrict__ bk,
    const float* __restrict__ bv)
{
    const float* bias;
    float* out;
    if (blockIdx.y == 0)      { bias = bq; out = g_Q; }
    else if (blockIdx.y == 1) { bias = bk; out = g_K; }
    else                      { bias = bv; out = g_V; }
    const unsigned* Whi = g_Wbhi + (size_t)blockIdx.y * (E_ / 2) * D_;
    const unsigned* Wlo = g_Wblo + (size_t)blockIdx.y * (E_ / 2) * D_;

    // As: [stage][row 64][k2 8 + pad4] u32 ; stride 12 -> conflict-free frags
    // Bs: [stage][k2 8][n 64 + pad8] u32  ; stride 72 -> conflict-free frags
    __shared__ unsigned As_hi[2][64][12];
    __shared__ unsigned As_lo[2][64][12];
    __shared__ unsigned Bs_hi[2][8][72];
    __shared__ unsigned Bs_lo[2][8][72];

    const int tid  = threadIdx.x;
    const int lane = tid & 31;
    const int wid  = tid >> 5;
    const int wm   = wid >> 1;     // 0..3
    const int wn   = wid & 1;      // 0..1
    const int rowBase = blockIdx.x * BM;

    // global load coords
    const int arow = tid >> 2;          // 0..63
    const int ac2  = (tid & 3) * 2;     // u32 col 0,2,4,6
    const int bkk  = tid >> 5;          // 0..7
    const int bn2  = (tid & 31) * 2;    // 0..62

    const unsigned* aph = g_xhi + (size_t)(rowBase + arow) * (E_ / 2) + ac2;
    const unsigned* apl = g_xlo + (size_t)(rowBase + arow) * (E_ / 2) + ac2;
    const unsigned* bph = Whi + (size_t)bkk * D_ + bn2;
    const unsigned* bpl = Wlo + (size_t)bkk * D_ + bn2;

    float acc[4][4];
#pragma unroll
    for (int nt = 0; nt < 4; nt++)
#pragma unroll
        for (int k = 0; k < 4; k++) acc[nt][k] = 0.f;

    const int r  = lane >> 2;
    const int cc = lane & 3;
    const int m0 = wm * 16;
    const int n0 = wn * 32;

    uint2 pah, pal, pbh, pbl;

    auto store_tile = [&](int st) {
        *(uint2*)&As_hi[st][arow][ac2] = pah;
        *(uint2*)&As_lo[st][arow][ac2] = pal;
        *(uint2*)&Bs_hi[st][bkk][bn2] = pbh;
        *(uint2*)&Bs_lo[st][bkk][bn2] = pbl;
    };

    auto compute_tile = [&](int st) {
        unsigned ah[4], al[4];
        ah[0] = As_hi[st][m0 + r][cc];
        ah[1] = As_hi[st][m0 + r + 8][cc];
        ah[2] = As_hi[st][m0 + r][cc + 4];
        ah[3] = As_hi[st][m0 + r + 8][cc + 4];
        al[0] = As_lo[st][m0 + r][cc];
        al[1] = As_lo[st][m0 + r + 8][cc];
        al[2] = As_lo[st][m0 + r][cc + 4];
        al[3] = As_lo[st][m0 + r + 8][cc + 4];

        unsigned bh[4][2], bl[4][2];
#pragma unroll
        for (int nt = 0; nt < 4; nt++) {
            const int n = n0 + nt * 8 + r;
            bh[nt][0] = Bs_hi[st][cc][n];
            bh[nt][1] = Bs_hi[st][cc + 4][n];
            bl[nt][0] = Bs_lo[st][cc][n];
            bl[nt][1] = Bs_lo[st][cc + 4][n];
        }
        // dep distance 4: all hh, then all lh, then all hl
#pragma unroll
        for (int nt = 0; nt < 4; nt++) mma_bf16(acc[nt], ah, bh[nt]);
#pragma unroll
        for (int nt = 0; nt < 4; nt++) mma_bf16(acc[nt], al, bh[nt]);
#pragma unroll
        for (int nt = 0; nt < 4; nt++) mma_bf16(acc[nt], ah, bl[nt]);
    };

    // prologue: tile 0 -> stage 0
    pah = *(const uint2*)(aph);
    pal = *(const uint2*)(apl);
    pbh = *(const uint2*)(bph);
    pbl = *(const uint2*)(bpl);
    store_tile(0);
    __syncthreads();

    const int KTILES = E_ / BK;   // 64
    for (int kt = 1; kt < KTILES; kt++) {
        pah = *(const uint2*)(aph + kt * 8);
        pal = *(const uint2*)(apl + kt * 8);
        pbh = *(const uint2*)(bph + (size_t)kt * 8 * D_);
        pbl = *(const uint2*)(bpl + (size_t)kt * 8 * D_);

        compute_tile((kt - 1) & 1);
        store_tile(kt & 1);            // other buffer: fenced by previous sync
        __syncthreads();
    }
    compute_tile((KTILES - 1) & 1);

    // epilogue: bias + store
#pragma unroll
    for (int nt = 0; nt < 4; nt++) {
        const int col = n0 + nt * 8 + 2 * cc;
        const float b0v = bias[col];
        const float b1v = bias[col + 1];
        const int row0 = rowBase + m0 + r;
        float2 v0 = make_float2(acc[nt][0] + b0v, acc[nt][1] + b1v);
        float2 v1 = make_float2(acc[nt][2] + b0v, acc[nt][3] + b1v);
        *(float2*)&out[(size_t)row0 * D_ + col] = v0;
        *(float2*)&out[(size_t)(row0 + 8) * D_ + col] = v1;
    }
}

// ---------------------------------------------------------------------------
// Kernel 2: per-batch partial V row-sums. grid = B*16, block = (64, 4).
// ---------------------------------------------------------------------------
__global__ void vsum_partial()
{
    __shared__ float sm[4][D_];
    const int b = blockIdx.x >> 4;
    const int p = blockIdx.x & 15;
    const int d = threadIdx.x;
    const int g = threadIdx.y;

    float s = 0.f;
    const float* base = g_V + ((size_t)b * S_ + (size_t)p * 256 + g) * D_ + d;
#pragma unroll 8
    for (int rr = 0; rr < 64; rr++) s += base[(size_t)rr * 4 * D_];
    sm[g][d] = s;
    __syncthreads();
    if (g == 0) {
        float t = sm[0][d] + sm[1][d] + sm[2][d] + sm[3][d];
        g_part[(b * 16 + p) * D_ + d] = t;
    }
}

// ---------------------------------------------------------------------------
// Kernel 3: windowed attention combine. One warp per (b, i).
// out[i] = [ e0*Vsum + sum_w (e_w - e0)*V[j_w] ] / [ sum_w e_w + e0*(S - n_valid) ]
// ---------------------------------------------------------------------------
__global__ __launch_bounds__(256) void attn_kernel(float* __restrict__ out)
{
    const int gw = (blockIdx.x * blockDim.x + threadIdx.x) >> 5;
    const int lane = threadIdx.x & 31;
    if (gw >= B_ * S_) return;

    const int b = gw >> 12;
    const int i = gw & (S_ - 1);

    const float* Qr = g_Q + (size_t)gw * D_;
    const float q0 = Qr[lane];
    const float q1 = Qr[lane + 32];

    float c[WIN_];
    bool valid[WIN_];
    int jv[WIN_];
    int nv = 0;
    float cmax = 0.f;

#pragma unroll
    for (int w = 0; w < WIN_; w++) {
        const int j = i + DIL_ * (w - WIN_ / 2);
        jv[w] = j;
        valid[w] = (j >= 0) && (j < S_);
        float p = 0.f;
        if (valid[w]) {
            const float* Kr = g_K + ((size_t)b * S_ + j) * D_;
            p = q0 * Kr[lane] + q1 * Kr[lane + 32];
#pragma unroll
            for (int o = 16; o > 0; o >>= 1)
                p += __shfl_xor_sync(0xffffffffu, p, o);
            nv++;
            cmax = fmaxf(cmax, p);
        }
        c[w] = p;
    }

    float vs0 = 0.f, vs1 = 0.f;
    const float* pp = g_part + b * 16 * D_;
#pragma unroll
    for (int p = 0; p < 16; p++) {
        vs0 += pp[p * D_ + lane];
        vs1 += pp[p * D_ + lane + 32];
    }

    const float e0 = expf(-cmax);
    float denom = e0 * (float)(S_ - nv);
    float acc0 = e0 * vs0;
    float acc1 = e0 * vs1;

#pragma unroll
    for (int w = 0; w < WIN_; w++) {
        if (valid[w]) {
            const float ew = expf(c[w] - cmax);
            denom += ew;
            const float f = ew - e0;
            const float* Vr = g_V + ((size_t)b * S_ + jv[w]) * D_;
            acc0 = fmaf(f, Vr[lane], acc0);
            acc1 = fmaf(f, Vr[lane + 32], acc1);
        }
    }

    const float inv = 1.f / denom;
    out[(size_t)gw * D_ + lane] = acc0 * inv;
    out[(size_t)gw * D_ + lane + 32] = acc1 * inv;
}

// ---------------------------------------------------------------------------
extern "C" void kernel_launch(void* const* d_in, const int* in_sizes, int n_in,
                              void* d_out, int out_size)
{
    const float* x  = (const float*)d_in[0];
    const float* Wq = (const float*)d_in[1];
    const float* bq = (const float*)d_in[2];
    const float* Wk = (const float*)d_in[3];
    const float* bk = (const float*)d_in[4];
    const float* Wv = (const float*)d_in[5];
    const float* bv = (const float*)d_in[6];
    float* out = (float*)d_out;

    xsplit_kernel<<<B_ * S_, 256>>>(x);
    wsplit_kernel<<<(3 * (E_ / 2) * D_ + 255) / 256, 256>>>(Wq, Wk, Wv);

    dim3 gg((B_ * S_) / BM, 3);
    qkv_gemm_bf16<<<gg, 256>>>(bq, bk, bv);

    vsum_partial<<<B_ * 16, dim3(D_, 4)>>>();

    const int warps = B_ * S_;
    attn_kernel<<<(warps * 32 + 255) / 256, 256>>>(out);
}

// round 8
// speedup vs baseline: 1.6434x; 1.3369x over previous
#include <cuda_runtime.h>
#include <cuda_bf16.h>
#include <math.h>

#define B_ 2
#define S_ 4096
#define E_ 1024
#define D_ 64
#define WIN_ 5
#define DIL_ 2

// Scratch (allocation-free rule: __device__ globals)
__device__ float g_Q[B_ * S_ * D_];
__device__ float g_K[B_ * S_ * D_];
__device__ float g_V[B_ * S_ * D_];
__device__ float g_part2[B_ * 64 * D_];
__device__ float g_Vsum[B_ * D_];
// W merged+split: [k/2][col], col = mat*64 + n, packed bf16 pairs {2k2, 2k2+1}
__device__ unsigned g_Wbhi[(E_ / 2) * 192];
__device__ unsigned g_Wblo[(E_ / 2) * 192];

// ---------------------------------------------------------------------------
// bf16 helpers
// ---------------------------------------------------------------------------
__device__ __forceinline__ unsigned pack_bf16(float lo_val, float hi_val) {
    __nv_bfloat162 p;
    p.x = __float2bfloat16(lo_val);   // low 16 bits  (k even)
    p.y = __float2bfloat16(hi_val);   // high 16 bits (k odd)
    return *(unsigned*)&p;
}
__device__ __forceinline__ float bf_residual(float v) {
    __nv_bfloat16 h = __float2bfloat16(v);
    return v - __bfloat162float(h);
}
__device__ __forceinline__ void mma_bf16(float* c, const unsigned* a, const unsigned* b) {
    asm volatile(
        "mma.sync.aligned.m16n8k16.row.col.f32.bf16.bf16.f32 "
        "{%0,%1,%2,%3}, {%4,%5,%6,%7}, {%8,%9}, {%0,%1,%2,%3};"
        : "+f"(c[0]), "+f"(c[1]), "+f"(c[2]), "+f"(c[3])
        : "r"(a[0]), "r"(a[1]), "r"(a[2]), "r"(a[3]), "r"(b[0]), "r"(b[1]));
}

// ---------------------------------------------------------------------------
// Kernel 0: W -> merged packed bf16 hi/lo planes, [k/2][mat*64+n].
// ---------------------------------------------------------------------------
__global__ void wsplit_kernel(const float* __restrict__ Wq,
                              const float* __restrict__ Wk,
                              const float* __restrict__ Wv)
{
    const int idx = blockIdx.x * blockDim.x + threadIdx.x;
    if (idx >= (E_ / 2) * 192) return;
    const int k2 = idx / 192;
    const int c  = idx - k2 * 192;
    const int mat = c >> 6;
    const int n = c & 63;
    const float* src = (mat == 0) ? Wq : (mat == 1) ? Wk : Wv;
    const float v0 = src[(2 * k2) * D_ + n];
    const float v1 = src[(2 * k2 + 1) * D_ + n];
    g_Wbhi[idx] = pack_bf16(v0, v1);
    g_Wblo[idx] = pack_bf16(bf_residual(v0), bf_residual(v1));
}

// ---------------------------------------------------------------------------
// Kernel 1: MERGED QKV GEMM, 3xBF16 (hh+lh+hl) on m16n8k16.
// C[8192 x 192] = x[8192 x 1024] @ W[1024 x 192] + bias; cols 0-63 -> Q,
// 64-127 -> K, 128-191 -> V. BM=64, BN=192, BK=16, 256 threads = 8 warps
// (2m x 4n), warp tile 32x48. A bf16-split at STS time (once per element).
// ---------------------------------------------------------------------------
#define BM 64
#define PB 200   // Bs row pad: bank = 8*cc + r, all 32 distinct

__global__ __launch_bounds__(256) void qkv_gemm_merged(
    const float* __restrict__ x,
    const float* __restrict__ bq,
    const float* __restrict__ bk,
    const float* __restrict__ bv)
{
    __shared__ unsigned As_hi[2][64][12];
    __shared__ unsigned As_lo[2][64][12];
    __shared__ unsigned Bs_hi[2][8][PB];
    __shared__ unsigned Bs_lo[2][8][PB];

    const int tid  = threadIdx.x;
    const int lane = tid & 31;
    const int wid  = tid >> 5;
    const int wm   = wid >> 2;      // 0..1 -> m0 = wm*32
    const int wn   = wid & 3;       // 0..3 -> n0 = wn*48
    const int rowBase = blockIdx.x * BM;

    // A global: 64 rows x 4 float4; thread -> (row, quarter)
    const int arow = tid >> 2;          // 0..63
    const int af   = tid & 3;           // float4 index 0..3
    // B global: k2 = tid>>5 (0..7), two cols per thread, 3 column-iterations
    const int bk2 = tid >> 5;
    const int bc  = (tid & 31) * 2;

    const float* aptr = x + (size_t)(rowBase + arow) * E_ + af * 4;

    float acc[2][6][4];
#pragma unroll
    for (int mt = 0; mt < 2; mt++)
#pragma unroll
        for (int nt = 0; nt < 6; nt++)
#pragma unroll
            for (int k = 0; k < 4; k++) acc[mt][nt][k] = 0.f;

    const int r  = lane >> 2;
    const int cc = lane & 3;
    const int m0 = wm * 32;
    const int n0 = wn * 48;

    float4 pa;
    uint2 pbh[3], pbl[3];

    auto load_tile = [&](int kt) {
        pa = *(const float4*)(aptr + kt * 16);
        const unsigned* wh = g_Wbhi + (size_t)(kt * 8 + bk2) * 192;
        const unsigned* wl = g_Wblo + (size_t)(kt * 8 + bk2) * 192;
#pragma unroll
        for (int it = 0; it < 3; it++) {
            pbh[it] = *(const uint2*)(wh + it * 64 + bc);
            pbl[it] = *(const uint2*)(wl + it * 64 + bc);
        }
    };

    auto store_tile = [&](int st) {
        uint2 h, l;
        h.x = pack_bf16(pa.x, pa.y);
        h.y = pack_bf16(pa.z, pa.w);
        l.x = pack_bf16(bf_residual(pa.x), bf_residual(pa.y));
        l.y = pack_bf16(bf_residual(pa.z), bf_residual(pa.w));
        *(uint2*)&As_hi[st][arow][af * 2] = h;
        *(uint2*)&As_lo[st][arow][af * 2] = l;
#pragma unroll
        for (int it = 0; it < 3; it++) {
            *(uint2*)&Bs_hi[st][bk2][it * 64 + bc] = pbh[it];
            *(uint2*)&Bs_lo[st][bk2][it * 64 + bc] = pbl[it];
        }
    };

    auto compute_tile = [&](int st) {
        unsigned ah[2][4], al[2][4];
#pragma unroll
        for (int mt = 0; mt < 2; mt++) {
            const int mr = m0 + mt * 16 + r;
            ah[mt][0] = As_hi[st][mr][cc];
            ah[mt][1] = As_hi[st][mr + 8][cc];
            ah[mt][2] = As_hi[st][mr][cc + 4];
            ah[mt][3] = As_hi[st][mr + 8][cc + 4];
            al[mt][0] = As_lo[st][mr][cc];
            al[mt][1] = As_lo[st][mr + 8][cc];
            al[mt][2] = As_lo[st][mr][cc + 4];
            al[mt][3] = As_lo[st][mr + 8][cc + 4];
        }
        unsigned bh[6][2], bl[6][2];
#pragma unroll
        for (int nt = 0; nt < 6; nt++) {
            const int n = n0 + nt * 8 + r;
            bh[nt][0] = Bs_hi[st][cc][n];
            bh[nt][1] = Bs_hi[st][cc + 4][n];
            bl[nt][0] = Bs_lo[st][cc][n];
            bl[nt][1] = Bs_lo[st][cc + 4][n];
        }
        // 36 MMAs, dep distance 12 per accumulator
#pragma unroll
        for (int mt = 0; mt < 2; mt++)
#pragma unroll
            for (int nt = 0; nt < 6; nt++) mma_bf16(acc[mt][nt], ah[mt], bh[nt]);
#pragma unroll
        for (int mt = 0; mt < 2; mt++)
#pragma unroll
            for (int nt = 0; nt < 6; nt++) mma_bf16(acc[mt][nt], al[mt], bh[nt]);
#pragma unroll
        for (int mt = 0; mt < 2; mt++)
#pragma unroll
            for (int nt = 0; nt < 6; nt++) mma_bf16(acc[mt][nt], ah[mt], bl[nt]);
    };

    load_tile(0);
    store_tile(0);
    __syncthreads();

    const int KTILES = E_ / 16;   // 64
    for (int kt = 1; kt < KTILES; kt++) {
        load_tile(kt);
        compute_tile((kt - 1) & 1);
        store_tile(kt & 1);            // other buffer: fenced by previous sync
        __syncthreads();
    }
    compute_tile((KTILES - 1) & 1);

    // epilogue: route each 8-col group to Q/K/V with its bias
#pragma unroll
    for (int nt = 0; nt < 6; nt++) {
        const int colbase = n0 + nt * 8;        // 8-aligned -> single mat
        const int mat = colbase >> 6;
        const int ocolb = colbase & 63;
        float* op = (mat == 0) ? g_Q : (mat == 1) ? g_K : g_V;
        const float* bp = (mat == 0) ? bq : (mat == 1) ? bk : bv;
        const int ocol = ocolb + 2 * cc;
        const float b0v = bp[ocol];
        const float b1v = bp[ocol + 1];
#pragma unroll
        for (int mt = 0; mt < 2; mt++) {
            const int row0 = rowBase + m0 + mt * 16 + r;
            float2 v0 = make_float2(acc[mt][nt][0] + b0v, acc[mt][nt][1] + b1v);
            float2 v1 = make_float2(acc[mt][nt][2] + b0v, acc[mt][nt][3] + b1v);
            *(float2*)&op[(size_t)row0 * D_ + ocol] = v0;
            *(float2*)&op[(size_t)(row0 + 8) * D_ + ocol] = v1;
        }
    }
}

// ---------------------------------------------------------------------------
// Kernel 2a: partial V row-sums. grid = B*64, block (64,4): 64 rows/block.
// ---------------------------------------------------------------------------
__global__ void vsum_partial()
{
    __shared__ float sm[4][D_];
    const int b = blockIdx.x >> 6;
    const int p = blockIdx.x & 63;
    const int d = threadIdx.x;
    const int g = threadIdx.y;

    float s = 0.f;
    const float* base = g_V + ((size_t)b * S_ + (size_t)p * 64 + g) * D_ + d;
#pragma unroll
    for (int rr = 0; rr < 16; rr++) s += base[(size_t)rr * 4 * D_];
    sm[g][d] = s;
    __syncthreads();
    if (g == 0) {
        g_part2[((size_t)b * 64 + p) * D_ + d] = sm[0][d] + sm[1][d] + sm[2][d] + sm[3][d];
    }
}

// ---------------------------------------------------------------------------
// Kernel 2b: reduce 64 partials -> g_Vsum. grid = B, block (64,8).
// ---------------------------------------------------------------------------
__global__ void vsum_reduce()
{
    __shared__ float sm[8][D_];
    const int b = blockIdx.x;
    const int d = threadIdx.x;
    const int g = threadIdx.y;
    float s = 0.f;
#pragma unroll
    for (int j = 0; j < 8; j++)
        s += g_part2[((size_t)b * 64 + g * 8 + j) * D_ + d];
    sm[g][d] = s;
    __syncthreads();
    if (g == 0) {
        float t = 0.f;
#pragma unroll
        for (int k = 0; k < 8; k++) t += sm[k][d];
        g_Vsum[b * D_ + d] = t;
    }
}

// ---------------------------------------------------------------------------
// Kernel 3: windowed attention combine. One warp per (b, i).
// out[i] = [ e0*Vsum + sum_w (e_w - e0)*V[j_w] ] / [ sum_w e_w + e0*(S - n_valid) ]
// ---------------------------------------------------------------------------
__global__ __launch_bounds__(256) void attn_kernel(float* __restrict__ out)
{
    const int gw = (blockIdx.x * blockDim.x + threadIdx.x) >> 5;
    const int lane = threadIdx.x & 31;
    if (gw >= B_ * S_) return;

    const int b = gw >> 12;
    const int i = gw & (S_ - 1);

    const float* Qr = g_Q + (size_t)gw * D_;
    const float q0 = Qr[lane];
    const float q1 = Qr[lane + 32];

    float c[WIN_];
    bool valid[WIN_];
    int jv[WIN_];
    int nv = 0;
    float cmax = 0.f;

#pragma unroll
    for (int w = 0; w < WIN_; w++) {
        const int j = i + DIL_ * (w - WIN_ / 2);
        jv[w] = j;
        valid[w] = (j >= 0) && (j < S_);
        float p = 0.f;
        if (valid[w]) {
            const float* Kr = g_K + ((size_t)b * S_ + j) * D_;
            p = q0 * Kr[lane] + q1 * Kr[lane + 32];
#pragma unroll
            for (int o = 16; o > 0; o >>= 1)
                p += __shfl_xor_sync(0xffffffffu, p, o);
            nv++;
            cmax = fmaxf(cmax, p);
        }
        c[w] = p;
    }

    const float vs0 = g_Vsum[b * D_ + lane];
    const float vs1 = g_Vsum[b * D_ + lane + 32];

    const float e0 = expf(-cmax);
    float denom = e0 * (float)(S_ - nv);
    float acc0 = e0 * vs0;
    float acc1 = e0 * vs1;

#pragma unroll
    for (int w = 0; w < WIN_; w++) {
        if (valid[w]) {
            const float ew = expf(c[w] - cmax);
            denom += ew;
            const float f = ew - e0;
            const float* Vr = g_V + ((size_t)b * S_ + jv[w]) * D_;
            acc0 = fmaf(f, Vr[lane], acc0);
            acc1 = fmaf(f, Vr[lane + 32], acc1);
        }
    }

    const float inv = 1.f / denom;
    out[(size_t)gw * D_ + lane] = acc0 * inv;
    out[(size_t)gw * D_ + lane + 32] = acc1 * inv;
}

// ---------------------------------------------------------------------------
extern "C" void kernel_launch(void* const* d_in, const int* in_sizes, int n_in,
                              void* d_out, int out_size)
{
    const float* x  = (const float*)d_in[0];
    const float* Wq = (const float*)d_in[1];
    const float* bq = (const float*)d_in[2];
    const float* Wk = (const float*)d_in[3];
    const float* bk = (const float*)d_in[4];
    const float* Wv = (const float*)d_in[5];
    const float* bv = (const float*)d_in[6];
    float* out = (float*)d_out;

    wsplit_kernel<<<((E_ / 2) * 192 + 255) / 256, 256>>>(Wq, Wk, Wv);

    qkv_gemm_merged<<<(B_ * S_) / BM, 256>>>(x, bq, bk, bv);

    vsum_partial<<<B_ * 64, dim3(D_, 4)>>>();
    vsum_reduce<<<B_, dim3(D_, 8)>>>();

    const int warps = B_ * S_;
    attn_kernel<<<(warps * 32 + 255) / 256, 256>>>(out);
}

// round 9
// speedup vs baseline: 1.6939x; 1.0307x over previous
#include <cuda_runtime.h>
#include <cuda_bf16.h>
#include <math.h>

#define B_ 2
#define S_ 4096
#define E_ 1024
#define D_ 64
#define WIN_ 5
#define DIL_ 2

// Scratch (allocation-free rule: __device__ globals)
__device__ float g_Q[B_ * S_ * D_];
__device__ float g_K[B_ * S_ * D_];
__device__ float g_V[B_ * S_ * D_];
__device__ float g_Vsum[B_ * D_];
// W merged+split: [k/2][col], col = mat*64 + n, packed bf16 pairs {2k2, 2k2+1}
__device__ unsigned g_Wbhi[(E_ / 2) * 192];
__device__ unsigned g_Wblo[(E_ / 2) * 192];

// ---------------------------------------------------------------------------
// bf16 helpers
// ---------------------------------------------------------------------------
__device__ __forceinline__ unsigned pack_bf16(float lo_val, float hi_val) {
    __nv_bfloat162 p;
    p.x = __float2bfloat16(lo_val);
    p.y = __float2bfloat16(hi_val);
    return *(unsigned*)&p;
}
__device__ __forceinline__ float bf_residual(float v) {
    __nv_bfloat16 h = __float2bfloat16(v);
    return v - __bfloat162float(h);
}
__device__ __forceinline__ void mma_bf16(float* c, const unsigned* a, const unsigned* b) {
    asm volatile(
        "mma.sync.aligned.m16n8k16.row.col.f32.bf16.bf16.f32 "
        "{%0,%1,%2,%3}, {%4,%5,%6,%7}, {%8,%9}, {%0,%1,%2,%3};"
        : "+f"(c[0]), "+f"(c[1]), "+f"(c[2]), "+f"(c[3])
        : "r"(a[0]), "r"(a[1]), "r"(a[2]), "r"(a[3]), "r"(b[0]), "r"(b[1]));
}

// ---------------------------------------------------------------------------
// Kernel 0: W -> merged packed bf16 hi/lo planes, [k/2][mat*64+n].
// Also initializes g_Vsum with the bias contribution: S * bv[d].
// ---------------------------------------------------------------------------
__global__ void wsplit_kernel(const float* __restrict__ Wq,
                              const float* __restrict__ Wk,
                              const float* __restrict__ Wv,
                              const float* __restrict__ bv)
{
    const int idx = blockIdx.x * blockDim.x + threadIdx.x;
    if (blockIdx.x == 0 && threadIdx.x < B_ * D_) {
        g_Vsum[threadIdx.x] = (float)S_ * bv[threadIdx.x & (D_ - 1)];
    }
    if (idx >= (E_ / 2) * 192) return;
    const int k2 = idx / 192;
    const int c  = idx - k2 * 192;
    const int mat = c >> 6;
    const int n = c & 63;
    const float* src = (mat == 0) ? Wq : (mat == 1) ? Wk : Wv;
    const float v0 = src[(2 * k2) * D_ + n];
    const float v1 = src[(2 * k2 + 1) * D_ + n];
    g_Wbhi[idx] = pack_bf16(v0, v1);
    g_Wblo[idx] = pack_bf16(bf_residual(v0), bf_residual(v1));
}

// ---------------------------------------------------------------------------
// Kernel 1: MERGED QKV GEMM, 3xBF16 (hh+lh+hl) on m16n8k16, BK=32.
// C[8192 x 192] = x @ [Wq|Wk|Wv] + bias. BM=64, 256 thr = 8 warps (2m x 4n),
// warp tile 32x48, 72 MMAs per warp per K-tile, 32 K-tiles, 32 syncs.
// V-column sums fused into epilogue via warp-reduce + atomicAdd.
// Dynamic smem ~72KB, ping-pong stages.
// ---------------------------------------------------------------------------
#define BM 64
#define SA 20     // As row stride (u32): banks (20r+cc)%32 all distinct, 16B-align ok
#define SB 200    // Bs row stride (u32): banks (8cc+r)%32 all distinct

// u32 offsets in dynamic smem
#define OFF_AH(s) ((s) * 1280)
#define OFF_AL(s) (2560 + (s) * 1280)
#define OFF_BH(s) (5120 + (s) * 3200)
#define OFF_BL(s) (11520 + (s) * 3200)
#define SMEM_U32  17920

__global__ __launch_bounds__(256) void qkv_gemm_merged(
    const float* __restrict__ x,
    const float* __restrict__ bq,
    const float* __restrict__ bk,
    const float* __restrict__ bv)
{
    extern __shared__ unsigned sm[];

    const int tid  = threadIdx.x;
    const int lane = tid & 31;
    const int wid  = tid >> 5;
    const int wm   = wid >> 2;      // 0..1 -> m0 = wm*32
    const int wn   = wid & 3;       // 0..3 -> n0 = wn*48
    const int rowBase = blockIdx.x * BM;
    const int bb = rowBase >> 12;   // batch of this block (4096 rows/batch)

    // A global: 64 rows, 8 floats per thread (2 float4), 4 threads/row
    const int arow = tid >> 2;          // 0..63
    const int af   = tid & 3;           // 0..3
    const float* aptr = x + (size_t)(rowBase + arow) * E_ + af * 8;

    float acc[2][6][4];
#pragma unroll
    for (int mt = 0; mt < 2; mt++)
#pragma unroll
        for (int nt = 0; nt < 6; nt++)
#pragma unroll
            for (int k = 0; k < 4; k++) acc[mt][nt][k] = 0.f;

    const int r  = lane >> 2;
    const int cc = lane & 3;
    const int m0 = wm * 32;
    const int n0 = wn * 48;

    float4 pa0, pa1;
    uint2 pbh[6], pbl[6];

    auto load_tile = [&](int kt) {
        pa0 = *(const float4*)(aptr + kt * 32);
        pa1 = *(const float4*)(aptr + kt * 32 + 4);
        // B: plane = 16 k2-rows x 96 uint2; 256 threads x 6 uint2
        const unsigned* wh = g_Wbhi + (size_t)kt * 16 * 192;
        const unsigned* wl = g_Wblo + (size_t)kt * 16 * 192;
#pragma unroll
        for (int i = 0; i < 6; i++) {
            const int e = tid + 256 * i;        // 0..1535
            pbh[i] = *(const uint2*)(wh + e * 2);
            pbl[i] = *(const uint2*)(wl + e * 2);
        }
    };

    auto store_tile = [&](int st) {
        uint4 h, l;
        h.x = pack_bf16(pa0.x, pa0.y);
        h.y = pack_bf16(pa0.z, pa0.w);
        h.z = pack_bf16(pa1.x, pa1.y);
        h.w = pack_bf16(pa1.z, pa1.w);
        l.x = pack_bf16(bf_residual(pa0.x), bf_residual(pa0.y));
        l.y = pack_bf16(bf_residual(pa0.z), bf_residual(pa0.w));
        l.z = pack_bf16(bf_residual(pa1.x), bf_residual(pa1.y));
        l.w = pack_bf16(bf_residual(pa1.z), bf_residual(pa1.w));
        *(uint4*)&sm[OFF_AH(st) + arow * SA + af * 4] = h;
        *(uint4*)&sm[OFF_AL(st) + arow * SA + af * 4] = l;
#pragma unroll
        for (int i = 0; i < 6; i++) {
            const int e = tid + 256 * i;
            const int krow = e / 96;
            const int cu2 = e - krow * 96;
            *(uint2*)&sm[OFF_BH(st) + krow * SB + cu2 * 2] = pbh[i];
            *(uint2*)&sm[OFF_BL(st) + krow * SB + cu2 * 2] = pbl[i];
        }
    };

    auto compute_tile = [&](int st) {
        const unsigned* AH = sm + OFF_AH(st);
        const unsigned* AL = sm + OFF_AL(st);
        const unsigned* BH = sm + OFF_BH(st);
        const unsigned* BL = sm + OFF_BL(st);
#pragma unroll
        for (int ks = 0; ks < 2; ks++) {
            const int kc = ks * 8 + cc;
            unsigned ah[2][4], al[2][4];
#pragma unroll
            for (int mt = 0; mt < 2; mt++) {
                const int mr = m0 + mt * 16 + r;
                ah[mt][0] = AH[mr * SA + kc];
                ah[mt][1] = AH[(mr + 8) * SA + kc];
                ah[mt][2] = AH[mr * SA + kc + 4];
                ah[mt][3] = AH[(mr + 8) * SA + kc + 4];
                al[mt][0] = AL[mr * SA + kc];
                al[mt][1] = AL[(mr + 8) * SA + kc];
                al[mt][2] = AL[mr * SA + kc + 4];
                al[mt][3] = AL[(mr + 8) * SA + kc + 4];
            }
            unsigned bh[6][2], bl[6][2];
#pragma unroll
            for (int nt = 0; nt < 6; nt++) {
                const int n = n0 + nt * 8 + r;
                bh[nt][0] = BH[kc * SB + n];
                bh[nt][1] = BH[(kc + 4) * SB + n];
                bl[nt][0] = BL[kc * SB + n];
                bl[nt][1] = BL[(kc + 4) * SB + n];
            }
#pragma unroll
            for (int mt = 0; mt < 2; mt++)
#pragma unroll
                for (int nt = 0; nt < 6; nt++) mma_bf16(acc[mt][nt], ah[mt], bh[nt]);
#pragma unroll
            for (int mt = 0; mt < 2; mt++)
#pragma unroll
                for (int nt = 0; nt < 6; nt++) mma_bf16(acc[mt][nt], al[mt], bh[nt]);
#pragma unroll
            for (int mt = 0; mt < 2; mt++)
#pragma unroll
                for (int nt = 0; nt < 6; nt++) mma_bf16(acc[mt][nt], ah[mt], bl[nt]);
        }
    };

    load_tile(0);
    store_tile(0);
    __syncthreads();

    const int KTILES = E_ / 32;   // 32
    for (int kt = 1; kt < KTILES; kt++) {
        load_tile(kt);
        compute_tile((kt - 1) & 1);
        store_tile(kt & 1);            // other buffer: fenced by previous sync
        __syncthreads();
    }
    compute_tile((KTILES - 1) & 1);

    // epilogue: route 8-col groups to Q/K/V with bias; fuse V column sums
#pragma unroll
    for (int nt = 0; nt < 6; nt++) {
        const int colbase = n0 + nt * 8;
        const int mat = colbase >> 6;
        const int ocolb = colbase & 63;
        float* op = (mat == 0) ? g_Q : (mat == 1) ? g_K : g_V;
        const float* bp = (mat == 0) ? bq : (mat == 1) ? bk : bv;
        const int ocol = ocolb + 2 * cc;
        const float b0v = bp[ocol];
        const float b1v = bp[ocol + 1];
#pragma unroll
        for (int mt = 0; mt < 2; mt++) {
            const int row0 = rowBase + m0 + mt * 16 + r;
            float2 v0 = make_float2(acc[mt][nt][0] + b0v, acc[mt][nt][1] + b1v);
            float2 v1 = make_float2(acc[mt][nt][2] + b0v, acc[mt][nt][3] + b1v);
            *(float2*)&op[(size_t)row0 * D_ + ocol] = v0;
            *(float2*)&op[(size_t)(row0 + 8) * D_ + ocol] = v1;
        }
        if (mat == 2) {
            // column sums over this block's 64 rows (bias already in g_Vsum init)
            float s0 = acc[0][nt][0] + acc[0][nt][2] + acc[1][nt][0] + acc[1][nt][2];
            float s1 = acc[0][nt][1] + acc[0][nt][3] + acc[1][nt][1] + acc[1][nt][3];
#pragma unroll
            for (int o = 4; o < 32; o <<= 1) {
                s0 += __shfl_xor_sync(0xffffffffu, s0, o);
                s1 += __shfl_xor_sync(0xffffffffu, s1, o);
            }
            if (r == 0) {
                atomicAdd(&g_Vsum[bb * D_ + ocol], s0);
                atomicAdd(&g_Vsum[bb * D_ + ocol + 1], s1);
            }
        }
    }
}

// ---------------------------------------------------------------------------
// Kernel 2: windowed attention combine. One warp per (b, i).
// out[i] = [ e0*Vsum + sum_w (e_w - e0)*V[j_w] ] / [ sum_w e_w + e0*(S - n_valid) ]
// ---------------------------------------------------------------------------
__global__ __launch_bounds__(256) void attn_kernel(float* __restrict__ out)
{
    const int gw = (blockIdx.x * blockDim.x + threadIdx.x) >> 5;
    const int lane = threadIdx.x & 31;
    if (gw >= B_ * S_) return;

    const int b = gw >> 12;
    const int i = gw & (S_ - 1);

    const float* Qr = g_Q + (size_t)gw * D_;
    const float q0 = Qr[lane];
    const float q1 = Qr[lane + 32];

    float c[WIN_];
    bool valid[WIN_];
    int jv[WIN_];
    int nv = 0;
    float cmax = 0.f;

#pragma unroll
    for (int w = 0; w < WIN_; w++) {
        const int j = i + DIL_ * (w - WIN_ / 2);
        jv[w] = j;
        valid[w] = (j >= 0) && (j < S_);
        float p = 0.f;
        if (valid[w]) {
            const float* Kr = g_K + ((size_t)b * S_ + j) * D_;
            p = q0 * Kr[lane] + q1 * Kr[lane + 32];
#pragma unroll
            for (int o = 16; o > 0; o >>= 1)
                p += __shfl_xor_sync(0xffffffffu, p, o);
            nv++;
            cmax = fmaxf(cmax, p);
        }
        c[w] = p;
    }

    const float vs0 = g_Vsum[b * D_ + lane];
    const float vs1 = g_Vsum[b * D_ + lane + 32];

    const float e0 = expf(-cmax);
    float denom = e0 * (float)(S_ - nv);
    float acc0 = e0 * vs0;
    float acc1 = e0 * vs1;

#pragma unroll
    for (int w = 0; w < WIN_; w++) {
        if (valid[w]) {
            const float ew = expf(c[w] - cmax);
            denom += ew;
            const float f = ew - e0;
            const float* Vr = g_V + ((size_t)b * S_ + jv[w]) * D_;
            acc0 = fmaf(f, Vr[lane], acc0);
            acc1 = fmaf(f, Vr[lane + 32], acc1);
        }
    }

    const float inv = 1.f / denom;
    out[(size_t)gw * D_ + lane] = acc0 * inv;
    out[(size_t)gw * D_ + lane + 32] = acc1 * inv;
}

// ---------------------------------------------------------------------------
extern "C" void kernel_launch(void* const* d_in, const int* in_sizes, int n_in,
                              void* d_out, int out_size)
{
    const float* x  = (const float*)d_in[0];
    const float* Wq = (const float*)d_in[1];
    const float* bq = (const float*)d_in[2];
    const float* Wk = (const float*)d_in[3];
    const float* bk = (const float*)d_in[4];
    const float* Wv = (const float*)d_in[5];
    const float* bv = (const float*)d_in[6];
    float* out = (float*)d_out;

    static int configured = 0;
    if (!configured) {
        cudaFuncSetAttribute(qkv_gemm_merged,
                             cudaFuncAttributeMaxDynamicSharedMemorySize,
                             SMEM_U32 * 4);
        configured = 1;
    }

    wsplit_kernel<<<((E_ / 2) * 192 + 255) / 256, 256>>>(Wq, Wk, Wv, bv);

    qkv_gemm_merged<<<(B_ * S_) / BM, 256, SMEM_U32 * 4>>>(x, bq, bk, bv);

    const int warps = B_ * S_;
    attn_kernel<<<(warps * 32 + 255) / 256, 256>>>(out);
}